// round 4
// baseline (speedup 1.0000x reference)
#include <cuda_runtime.h>

#define HH 224
#define WW 224
#define HW (HH * WW)
#define BB 256
#define NTOT (BB * HW)
#define DTc 0.15f

#define TY 46                  // interior rows per tile
#define HALO 5                 // 5 fused steps per kernel
#define RR (TY + 2 * HALO)     // 56 data rows in tile
#define RPAIRS (RR / 2)        // 28 vertical row-pair packs
#define RPP (RPAIRS + 2)       // +2 zero-pad pack rows -> 30
#define TCOLS 112              // thread-columns (each owns 2 pixel cols)
#define PW2 114                // plane width incl 2 pads
#define ROWSTRIDE (2 * PW2)    // E plane then O plane per pack-row (228 cells)
#define TILES 5                // 5*46 = 230 >= 224
#define STRIPS 4
#define NTHREADS (TCOLS * STRIPS)    // 448
#define PACKS_PER (RPAIRS / STRIPS)  // 7
#define SMP (RPP * ROWSTRIDE)        // cells (ulonglong2) per buffer = 6840
#define SMEM_BYTES (2 * SMP * 16)    // 218880 B

typedef unsigned long long u64;

// Intermediate state between the two fused kernels (no allocs allowed).
__device__ float g_s[NTOT];
__device__ float g_c[NTOT];

// ---- packed f32x2 helpers ----
__device__ __forceinline__ u64 pk2(float lo, float hi) {
    u64 r; asm("mov.b64 %0, {%1, %2};" : "=l"(r) : "f"(lo), "f"(hi)); return r;
}
__device__ __forceinline__ void unpk2(u64 v, float& lo, float& hi) {
    asm("mov.b64 {%0, %1}, %2;" : "=f"(lo), "=f"(hi) : "l"(v));
}
// (a.hi, b.lo)
__device__ __forceinline__ u64 funnel(u64 a, u64 b) {
    u64 r;
    asm("{\n\t.reg .f32 al, ah, bl, bh;\n\t"
        "mov.b64 {al, ah}, %1;\n\t"
        "mov.b64 {bl, bh}, %2;\n\t"
        "mov.b64 %0, {ah, bl};\n\t}"
        : "=l"(r) : "l"(a), "l"(b));
    return r;
}
__device__ __forceinline__ u64 add2(u64 a, u64 b) {
    u64 d; asm("add.rn.f32x2 %0, %1, %2;" : "=l"(d) : "l"(a), "l"(b)); return d;
}
__device__ __forceinline__ u64 mul2(u64 a, u64 b) {
    u64 d; asm("mul.rn.f32x2 %0, %1, %2;" : "=l"(d) : "l"(a), "l"(b)); return d;
}
__device__ __forceinline__ u64 fma2(u64 a, u64 b, u64 c) {
    u64 d; asm("fma.rn.f32x2 %0, %1, %2, %3;" : "=l"(d) : "l"(a), "l"(b), "l"(c)); return d;
}
__device__ __forceinline__ u64 neg2(u64 a) { return a ^ 0x8000000080000000ULL; }

// Full per-pack rotation update given neighbor packs.
struct StepConsts { u64 DTK2, ONE2, C3, C5, C2, C4; };

__device__ __forceinline__ ulonglong2 cell_update(ulonglong2 prev, ulonglong2 cur,
                                                  ulonglong2 nxt, ulonglong2 lft,
                                                  ulonglong2 rgt, u64 dto,
                                                  const StepConsts& C) {
    u64 up_s = funnel(prev.x, cur.x);
    u64 up_c = funnel(prev.y, cur.y);
    u64 dn_s = funnel(cur.x, nxt.x);
    u64 dn_c = funnel(cur.y, nxt.y);

    u64 sn = add2(add2(up_s, dn_s), add2(lft.x, rgt.x));
    u64 cn = add2(add2(up_c, dn_c), add2(lft.y, rgt.y));

    u64 coup = fma2(cur.y, sn, neg2(mul2(cur.x, cn)));
    u64 d = fma2(C.DTK2, coup, dto);

    u64 d2 = mul2(d, d);
    u64 sd = mul2(d, fma2(d2, fma2(d2, C.C5, C.C3), C.ONE2));
    u64 cd = fma2(d2, fma2(d2, C.C4, C.C2), C.ONE2);

    ulonglong2 r;
    r.x = fma2(cur.x, cd, mul2(cur.y, sd));
    r.y = fma2(cur.y, cd, neg2(mul2(cur.x, sd)));
    return r;
}

template <int PHASE>  // 0: init from x_img -> g_s/g_c ; 1: g_s/g_c -> out
__global__ void __launch_bounds__(NTHREADS, 1)
fused5_kernel(const float* __restrict__ x_img,
              const float* __restrict__ omega,
              const float* __restrict__ Kp,
              float* __restrict__ out) {
    extern __shared__ ulonglong2 sm2[];
    ulonglong2* bufA = sm2;
    ulonglong2* bufB = sm2 + SMP;

    const int tid = threadIdx.x;
    const int t = tid % TCOLS;         // thread-column 0..111 (owns pixel cols 2t, 2t+1)
    const int strip = tid / TCOLS;     // 0..3
    const int r0p = 1 + strip * PACKS_PER;
    const int b = blockIdx.y;
    const int y0 = blockIdx.x * TY;
    const int xe = 2 * t;              // even pixel col

    const float DTK = DTc * Kp[0];
    StepConsts C;
    C.DTK2 = pk2(DTK, DTK);
    C.ONE2 = pk2(1.0f, 1.0f);
    C.C3 = pk2(-1.0f / 6.0f, -1.0f / 6.0f);
    C.C5 = pk2(8.3333333e-3f, 8.3333333e-3f);
    C.C2 = pk2(-0.5f, -0.5f);
    C.C4 = pk2(4.1666668e-2f, 4.1666668e-2f);

    // Zero both buffers (pads + out-of-image rows must be exactly 0).
    for (int i = tid; i < 2 * SMP; i += NTHREADS) sm2[i] = make_ulonglong2(0ULL, 0ULL);
    __syncthreads();

    // Plane cell indices for this thread.
    //  E-plane data j=1..112 <-> col 2(j-1); O-plane data j=1..112 <-> col 2j-1.
    const int iE = t + 1;              // own even col 2t
    const int iO = PW2 + t + 1;        // own odd col 2t+1
    const int iL = PW2 + t;            // left neighbor = col 2t-1  (t=0 -> pad)
    const int iR = t + 2;              // right neighbor = col 2t+2 (t=111 -> pad)

    // Per-pack DT*omega (as f32x2 over the row pair) for both owned columns,
    // plus initial state load into bufA. All global I/O is float2 (col-pair).
    u64 dtoE[PACKS_PER], dtoO[PACKS_PER];
#pragma unroll
    for (int j = 0; j < PACKS_PER; j++) {
        const int rp = r0p + j;
        const int rt0 = 2 * (rp - 1);
        const int gy0 = y0 - HALO + rt0;
        const int gy1 = gy0 + 1;
        const bool in0 = (gy0 >= 0) && (gy0 < HH);
        const bool in1 = (gy1 >= 0) && (gy1 < HH);

        float2 o0 = in0 ? *(const float2*)&omega[gy0 * WW + xe] : make_float2(0.f, 0.f);
        float2 o1 = in1 ? *(const float2*)&omega[gy1 * WW + xe] : make_float2(0.f, 0.f);
        dtoE[j] = pk2(DTc * o0.x, DTc * o1.x);
        dtoO[j] = pk2(DTc * o0.y, DTc * o1.y);

        float sE0 = 0.f, cE0 = 0.f, sO0 = 0.f, cO0 = 0.f;
        float sE1 = 0.f, cE1 = 0.f, sO1 = 0.f, cO1 = 0.f;
        if (PHASE == 0) {
            if (in0) {
                float2 v = *(const float2*)&x_img[b * HW + gy0 * WW + xe];
                sincospif(fmaf(2.0f, v.x, -1.0f), &sE0, &cE0);
                sincospif(fmaf(2.0f, v.y, -1.0f), &sO0, &cO0);
            }
            if (in1) {
                float2 v = *(const float2*)&x_img[b * HW + gy1 * WW + xe];
                sincospif(fmaf(2.0f, v.x, -1.0f), &sE1, &cE1);
                sincospif(fmaf(2.0f, v.y, -1.0f), &sO1, &cO1);
            }
        } else {
            if (in0) {
                float2 vs = *(const float2*)&g_s[b * HW + gy0 * WW + xe];
                float2 vc = *(const float2*)&g_c[b * HW + gy0 * WW + xe];
                sE0 = vs.x; sO0 = vs.y; cE0 = vc.x; cO0 = vc.y;
            }
            if (in1) {
                float2 vs = *(const float2*)&g_s[b * HW + gy1 * WW + xe];
                float2 vc = *(const float2*)&g_c[b * HW + gy1 * WW + xe];
                sE1 = vs.x; sO1 = vs.y; cE1 = vc.x; cO1 = vc.y;
            }
        }
        bufA[rp * ROWSTRIDE + iE] = make_ulonglong2(pk2(sE0, sE1), pk2(cE0, cE1));
        bufA[rp * ROWSTRIDE + iO] = make_ulonglong2(pk2(sO0, sO1), pk2(cO0, cO1));
    }
    __syncthreads();

    // 5 fused steps, ping-pong A<->B.
    const ulonglong2* p = bufA;
    ulonglong2* q = bufB;
#pragma unroll
    for (int st = 0; st < HALO; st++) {
        int base = r0p * ROWSTRIDE;
        ulonglong2 prevE = p[base - ROWSTRIDE + iE];
        ulonglong2 prevO = p[base - ROWSTRIDE + iO];
        ulonglong2 curE = p[base + iE];
        ulonglong2 curO = p[base + iO];
#pragma unroll
        for (int j = 0; j < PACKS_PER; j++) {
            ulonglong2 nxtE = p[base + ROWSTRIDE + iE];
            ulonglong2 nxtO = p[base + ROWSTRIDE + iO];
            ulonglong2 lft = p[base + iL];   // col 2t-1 (odd plane)
            ulonglong2 rgt = p[base + iR];   // col 2t+2 (even plane)

            // Even col: left = lft(2t-1), right = curO(2t+1) [register]
            ulonglong2 outE = cell_update(prevE, curE, nxtE, lft, curO, dtoE[j], C);
            // Odd col: left = curE(2t) [register], right = rgt(2t+2)
            ulonglong2 outO = cell_update(prevO, curO, nxtO, curE, rgt, dtoO[j], C);

            q[base + iE] = outE;
            q[base + iO] = outO;

            prevE = curE; prevO = curO;
            curE = nxtE; curO = nxtO;
            base += ROWSTRIDE;
        }
        __syncthreads();
        const ulonglong2* tp = q;
        q = (ulonglong2*)p;
        p = tp;
    }
    // Result now in p.

    // Write back interior rows (tile rows HALO..HALO+TY-1).
#pragma unroll
    for (int j = 0; j < PACKS_PER; j++) {
        const int rp = r0p + j;
        ulonglong2 vE = p[rp * ROWSTRIDE + iE];
        ulonglong2 vO = p[rp * ROWSTRIDE + iO];
        float sE0, sE1, cE0, cE1, sO0, sO1, cO0, cO1;
        unpk2(vE.x, sE0, sE1);
        unpk2(vE.y, cE0, cE1);
        unpk2(vO.x, sO0, sO1);
        unpk2(vO.y, cO0, cO1);
        const int rt0 = 2 * (rp - 1);
#pragma unroll
        for (int par = 0; par < 2; par++) {
            const int rt = rt0 + par;
            if (rt >= HALO && rt < HALO + TY) {
                const int gy = y0 + (rt - HALO);
                if (gy < HH) {
                    float ss0 = par ? sE1 : sE0;
                    float ss1 = par ? sO1 : sO0;
                    float vc0 = par ? cE1 : cE0;
                    float vc1 = par ? cO1 : cO0;
                    if (PHASE == 0) {
                        *(float2*)&g_s[b * HW + gy * WW + xe] = make_float2(ss0, ss1);
                        *(float2*)&g_c[b * HW + gy * WW + xe] = make_float2(vc0, vc1);
                    } else {
                        const int pix = gy * WW + xe;
                        *(float2*)&out[(long)b * (2 * HW) + pix] = make_float2(vc0, vc1);
                        *(float2*)&out[(long)b * (2 * HW) + HW + pix] = make_float2(ss0, ss1);
                    }
                }
            }
        }
    }
}

extern "C" void kernel_launch(void* const* d_in, const int* in_sizes, int n_in,
                              void* d_out, int out_size) {
    const float* x_img = (const float*)d_in[0];  // (B,1,H,W)
    const float* omega = (const float*)d_in[1];  // (1,1,H,W)
    const float* Kp    = (const float*)d_in[2];  // scalar
    float* out = (float*)d_out;

    static bool configured = false;
    if (!configured) {
        cudaFuncSetAttribute(fused5_kernel<0>,
                             cudaFuncAttributeMaxDynamicSharedMemorySize, SMEM_BYTES);
        cudaFuncSetAttribute(fused5_kernel<1>,
                             cudaFuncAttributeMaxDynamicSharedMemorySize, SMEM_BYTES);
        configured = true;
    }

    dim3 grid(TILES, BB);
    dim3 block(NTHREADS);
    fused5_kernel<0><<<grid, block, SMEM_BYTES>>>(x_img, omega, Kp, out);
    fused5_kernel<1><<<grid, block, SMEM_BYTES>>>(x_img, omega, Kp, out);
}

// round 5
// speedup vs baseline: 1.3594x; 1.3594x over previous
#include <cuda_runtime.h>

#define HH 224
#define WW 224
#define HW (HH * WW)
#define BB 256
#define NTOT (BB * HW)
#define DTc 0.15f
#define PIf 3.14159265358979f

#define TY 46                  // interior rows per tile
#define HALO 5                 // 5 fused steps per kernel
#define RR (TY + 2 * HALO)     // 56 data rows in tile
#define RPAIRS (RR / 2)        // 28 data row-pairs (packs)
#define RPP (RPAIRS + 2)       // +2 zero-pad pack rows -> 30
#define PWP (WW + 2)           // pack-row width in packs (226, incl col pads)
#define TILES 5                // 5*46 = 230 >= 224
#define NTHREADS 896           // 4 strips x 224 columns
#define STRIPS 4
#define PACKS_PER (RPAIRS / STRIPS)  // 7 packs per thread
#define SMP (RPP * PWP)        // ulonglong2 cells per buffer (6780)
#define SMEM_BYTES (2 * SMP * 16)    // 216960 B

typedef unsigned long long u64;

// Intermediate state between the two fused kernels (no allocs allowed).
__device__ float g_s[NTOT];
__device__ float g_c[NTOT];

// ---- packed f32x2 helpers ----
__device__ __forceinline__ u64 pk2(float lo, float hi) {
    u64 r; asm("mov.b64 %0, {%1, %2};" : "=l"(r) : "f"(lo), "f"(hi)); return r;
}
__device__ __forceinline__ void unpk2(u64 v, float& lo, float& hi) {
    asm("mov.b64 {%0, %1}, %2;" : "=f"(lo), "=f"(hi) : "l"(v));
}
// (a.hi, b.lo)
__device__ __forceinline__ u64 funnel(u64 a, u64 b) {
    u64 r;
    asm("{\n\t.reg .f32 al, ah, bl, bh;\n\t"
        "mov.b64 {al, ah}, %1;\n\t"
        "mov.b64 {bl, bh}, %2;\n\t"
        "mov.b64 %0, {ah, bl};\n\t}"
        : "=l"(r) : "l"(a), "l"(b));
    return r;
}
__device__ __forceinline__ u64 add2(u64 a, u64 b) {
    u64 d; asm("add.rn.f32x2 %0, %1, %2;" : "=l"(d) : "l"(a), "l"(b)); return d;
}
__device__ __forceinline__ u64 mul2(u64 a, u64 b) {
    u64 d; asm("mul.rn.f32x2 %0, %1, %2;" : "=l"(d) : "l"(a), "l"(b)); return d;
}
__device__ __forceinline__ u64 fma2(u64 a, u64 b, u64 c) {
    u64 d; asm("fma.rn.f32x2 %0, %1, %2, %3;" : "=l"(d) : "l"(a), "l"(b), "l"(c)); return d;
}
__device__ __forceinline__ u64 neg2(u64 a) { return a ^ 0x8000000080000000ULL; }

template <int PHASE>  // 0: init from x_img -> g_s/g_c ; 1: g_s/g_c -> out
__global__ void __launch_bounds__(NTHREADS, 1)
fused5_kernel(const float* __restrict__ x_img,
              const float* __restrict__ omega,
              const float* __restrict__ Kp,
              float* __restrict__ out) {
    extern __shared__ ulonglong2 sm2[];
    ulonglong2* bufA = sm2;
    ulonglong2* bufB = sm2 + SMP;

    const int tid = threadIdx.x;
    const int x = tid % WW;            // column 0..223
    const int strip = tid / WW;        // 0..3
    const int r0p = 1 + strip * PACKS_PER;
    const int xc = x + 1;
    const int b = blockIdx.y;
    const int y0 = blockIdx.x * TY;
    const float DTK = DTc * Kp[0];
    const u64 DTK2 = pk2(DTK, DTK);
    const u64 ONE2 = pk2(1.0f, 1.0f);
    const u64 C3 = pk2(-1.0f / 6.0f, -1.0f / 6.0f);
    const u64 C5 = pk2(8.3333333e-3f, 8.3333333e-3f);
    const u64 C2 = pk2(-0.5f, -0.5f);
    const u64 C4 = pk2(4.1666668e-2f, 4.1666668e-2f);

    // Zero ONLY the pad ring of both buffers (every data cell is rewritten
    // each step; zero cells rotate to zero so out-of-image rows stay 0).
    const ulonglong2 Z = make_ulonglong2(0ULL, 0ULL);
    for (int i = tid; i < PWP; i += NTHREADS) {
        bufA[i] = Z; bufA[(RPP - 1) * PWP + i] = Z;
        bufB[i] = Z; bufB[(RPP - 1) * PWP + i] = Z;
    }
    for (int r = tid; r < RPP; r += NTHREADS) {
        bufA[r * PWP] = Z; bufA[r * PWP + PWP - 1] = Z;
        bufB[r * PWP] = Z; bufB[r * PWP + PWP - 1] = Z;
    }

    // Per-pack DT*omega (0 outside image) + load initial state into bufA
    // (unconditional store: out-of-image rows get exact zeros).
    u64 dto2[PACKS_PER];
#pragma unroll
    for (int j = 0; j < PACKS_PER; j++) {
        const int rp = r0p + j;
        const int rt0 = 2 * (rp - 1);          // tile row of lo element
        const int gy0 = y0 - HALO + rt0;
        const int gy1 = gy0 + 1;
        const bool in0 = (gy0 >= 0) && (gy0 < HH);
        const bool in1 = (gy1 >= 0) && (gy1 < HH);
        float o0 = in0 ? DTc * omega[gy0 * WW + x] : 0.0f;
        float o1 = in1 ? DTc * omega[gy1 * WW + x] : 0.0f;
        dto2[j] = pk2(o0, o1);

        float s0 = 0.0f, c0 = 0.0f, s1 = 0.0f, c1 = 0.0f;
        if (PHASE == 0) {
            // theta0 = pi*(2x-1) in [-pi, pi]: hardware sincos is plenty accurate.
            if (in0) __sincosf(fmaf(2.0f * PIf, x_img[b * HW + gy0 * WW + x], -PIf), &s0, &c0);
            if (in1) __sincosf(fmaf(2.0f * PIf, x_img[b * HW + gy1 * WW + x], -PIf), &s1, &c1);
        } else {
            if (in0) { s0 = g_s[b * HW + gy0 * WW + x]; c0 = g_c[b * HW + gy0 * WW + x]; }
            if (in1) { s1 = g_s[b * HW + gy1 * WW + x]; c1 = g_c[b * HW + gy1 * WW + x]; }
        }
        bufA[rp * PWP + xc] = make_ulonglong2(pk2(s0, s1), pk2(c0, c1));
    }
    __syncthreads();

    // 5 fused steps, ping-pong A<->B.
    const ulonglong2* p = bufA;
    ulonglong2* q = bufB;
#pragma unroll
    for (int st = 0; st < HALO; st++) {
        int idx = r0p * PWP + xc;
        ulonglong2 prev = p[idx - PWP];
        ulonglong2 cur = p[idx];
        // Carried partial vertical sums: u = prev + cur (per field).
        u64 u_s = add2(prev.x, cur.x);
        u64 u_c = add2(prev.y, cur.y);
#pragma unroll
        for (int j = 0; j < PACKS_PER; j++) {
            ulonglong2 nxt = p[idx + PWP];
            ulonglong2 lft = p[idx - 1];
            ulonglong2 rgt = p[idx + 1];

            u64 v_s = add2(cur.x, nxt.x);
            u64 v_c = add2(cur.y, nxt.y);
            // up+down neighbor sum = (u.hi, v.lo)
            u64 sn = add2(funnel(u_s, v_s), add2(lft.x, rgt.x));
            u64 cn = add2(funnel(u_c, v_c), add2(lft.y, rgt.y));

            // coupling = cos*sn - sin*cn
            u64 coup = fma2(cur.y, sn, neg2(mul2(cur.x, cn)));
            u64 d = fma2(DTK2, coup, dto2[j]);

            // |d| <= 0.3: Taylor sin/cos, err ~4e-8
            u64 d2 = mul2(d, d);
            u64 sd = mul2(d, fma2(d2, fma2(d2, C5, C3), ONE2));
            u64 cd = fma2(d2, fma2(d2, C4, C2), ONE2);

            u64 ns = fma2(cur.x, cd, mul2(cur.y, sd));
            u64 nc = fma2(cur.y, cd, neg2(mul2(cur.x, sd)));
            q[idx] = make_ulonglong2(ns, nc);

            u_s = v_s; u_c = v_c;
            cur = nxt;
            idx += PWP;
        }
        __syncthreads();
        const ulonglong2* t = q;
        q = (ulonglong2*)p;
        p = t;
    }
    // Result now in p.

    // Write back interior rows (tile rows HALO..HALO+TY-1).
#pragma unroll
    for (int j = 0; j < PACKS_PER; j++) {
        const int rp = r0p + j;
        ulonglong2 v = p[rp * PWP + xc];
        float s0, s1, c0, c1;
        unpk2(v.x, s0, s1);
        unpk2(v.y, c0, c1);
        const int rt0 = 2 * (rp - 1);
#pragma unroll
        for (int par = 0; par < 2; par++) {
            const int rt = rt0 + par;
            if (rt >= HALO && rt < HALO + TY) {
                const int gy = y0 + (rt - HALO);
                if (gy < HH) {
                    const float s = par ? s1 : s0;
                    const float c = par ? c1 : c0;
                    if (PHASE == 0) {
                        const int gi = b * HW + gy * WW + x;
                        g_s[gi] = s;
                        g_c[gi] = c;
                    } else {
                        const int pix = gy * WW + x;
                        out[(long)b * (2 * HW) + pix] = c;       // cos channel
                        out[(long)b * (2 * HW) + HW + pix] = s;  // sin channel
                    }
                }
            }
        }
    }
}

extern "C" void kernel_launch(void* const* d_in, const int* in_sizes, int n_in,
                              void* d_out, int out_size) {
    const float* x_img = (const float*)d_in[0];  // (B,1,H,W)
    const float* omega = (const float*)d_in[1];  // (1,1,H,W)
    const float* Kp    = (const float*)d_in[2];  // scalar
    float* out = (float*)d_out;

    static bool configured = false;
    if (!configured) {
        cudaFuncSetAttribute(fused5_kernel<0>,
                             cudaFuncAttributeMaxDynamicSharedMemorySize, SMEM_BYTES);
        cudaFuncSetAttribute(fused5_kernel<1>,
                             cudaFuncAttributeMaxDynamicSharedMemorySize, SMEM_BYTES);
        configured = true;
    }

    dim3 grid(TILES, BB);
    dim3 block(NTHREADS);
    fused5_kernel<0><<<grid, block, SMEM_BYTES>>>(x_img, omega, Kp, out);
    fused5_kernel<1><<<grid, block, SMEM_BYTES>>>(x_img, omega, Kp, out);
}